// round 9
// baseline (speedup 1.0000x reference)
#include <cuda_runtime.h>
#include <cuda_fp16.h>
#include <math.h>
#include <stdint.h>

// R9: phase-by-reuse-class + FFMA2 MLP.
//  - Levels 0-6 in one kernel (hash footprint ~70MB, lambda>>1 -> L2 phased).
//  - Level 7 alone (~85MB, lambda~2).
//  - Levels 8-19 in ONE kernel: traffic there is compulsory (lambda<=1/sector),
//    so what matters is latency hiding (96 loads/thread) not residency.
//  - MLP packed with fma.rn.f32x2 (FFMA2): bit-identical accumulation order,
//    2x fp32 FMA throughput. Feature scratch uses streaming hints.

#define NLVL   20
#define LOG2T  24
#define TMASK  ((1u << LOG2T) - 1u)
#define PRIME1 2654435761u
#define PRIME2 805459861u
#define INDIM  40
#define HID    64
#define NPTS   524288

struct ResParams { float r[NLVL]; };

__device__ __half2 g_feat[NLVL * NPTS];   // level-major scratch (42 MB)

__device__ __forceinline__ float h_rt(float v) {
    return __half2float(__float2half_rn(v));
}

__device__ __forceinline__ bool probe_f32(const void* W2_) {
    const float* w2p = (const float*)W2_;
    int votes = 0;
    #pragma unroll
    for (int i = 0; i < 8; ++i) {
        const float v = __ldg(w2p + i);
        if (isfinite(v) && fabsf(v) >= 2e-3f && fabsf(v) <= 8.0f) ++votes;
    }
    return votes >= 4;
}

// ---- f32x2 packed helpers (FFMA2) ----
__device__ __forceinline__ uint64_t pk2(float lo, float hi) {
    uint64_t r; asm("mov.b64 %0, {%1,%2};" : "=l"(r) : "f"(lo), "f"(hi)); return r;
}
__device__ __forceinline__ float2 upk2(uint64_t v) {
    float2 f; asm("mov.b64 {%0,%1}, %2;" : "=f"(f.x), "=f"(f.y) : "l"(v)); return f;
}
__device__ __forceinline__ void ffma2(uint64_t& d, uint64_t a, uint64_t b) {
    asm("fma.rn.f32x2 %0, %1, %2, %0;" : "+l"(d) : "l"(a), "l"(b));
}

// ---------------- encode: NL levels starting at l0 ----------------
template <int NL>
__global__ __launch_bounds__(256) void k_encode(
    const float* __restrict__ xin,
    const void*  __restrict__ table_,
    const void*  __restrict__ W2_,
    int l0, int n, ResParams rp)
{
    const int pt = blockIdx.x * 256 + threadIdx.x;
    if (pt >= n) return;

    const bool f32mode = probe_f32(W2_);

    const float px = __ldg(xin + 3 * pt + 0);
    const float py = __ldg(xin + 3 * pt + 1);
    const float pz = __ldg(xin + 3 * pt + 2);

    #pragma unroll
    for (int ll = 0; ll < NL; ++ll) {
        const int li = l0 + ll;
        const float rf = rp.r[li];
        const float fx = px * rf, fy = py * rf, fz = pz * rf;
        const float gx = floorf(fx), gy = floorf(fy), gz = floorf(fz);
        const float dx = fx - gx, dy = fy - gy, dz = fz - gz;
        const unsigned bx = (unsigned)gx;
        const unsigned by = (unsigned)gy;
        const unsigned bz = (unsigned)gz;
        const unsigned hy0 = by * PRIME1, hy1 = hy0 + PRIME1;
        const unsigned hz0 = bz * PRIME2, hz1 = hz0 + PRIME2;
        const unsigned bx1 = bx + 1u;

        const unsigned i0 = (bx  ^ hy0 ^ hz0) & TMASK;
        const unsigned i1 = (bx1 ^ hy0 ^ hz0) & TMASK;
        const unsigned i2 = (bx  ^ hy1 ^ hz0) & TMASK;
        const unsigned i3 = (bx1 ^ hy1 ^ hz0) & TMASK;
        const unsigned i4 = (bx  ^ hy0 ^ hz1) & TMASK;
        const unsigned i5 = (bx1 ^ hy0 ^ hz1) & TMASK;
        const unsigned i6 = (bx  ^ hy1 ^ hz1) & TMASK;
        const unsigned i7 = (bx1 ^ hy1 ^ hz1) & TMASK;

        __half2 t0, t1, t2, t3, t4, t5, t6, t7;
        if (f32mode) {
            const float2* __restrict__ tb = (const float2*)table_ + ((size_t)li << LOG2T);
            const float2 f0 = __ldg(tb + i0);
            const float2 f1 = __ldg(tb + i1);
            const float2 f2 = __ldg(tb + i2);
            const float2 f3 = __ldg(tb + i3);
            const float2 f4 = __ldg(tb + i4);
            const float2 f5 = __ldg(tb + i5);
            const float2 f6 = __ldg(tb + i6);
            const float2 f7 = __ldg(tb + i7);
            t0 = __floats2half2_rn(f0.x, f0.y);
            t1 = __floats2half2_rn(f1.x, f1.y);
            t2 = __floats2half2_rn(f2.x, f2.y);
            t3 = __floats2half2_rn(f3.x, f3.y);
            t4 = __floats2half2_rn(f4.x, f4.y);
            t5 = __floats2half2_rn(f5.x, f5.y);
            t6 = __floats2half2_rn(f6.x, f6.y);
            t7 = __floats2half2_rn(f7.x, f7.y);
        } else {
            const __half2* __restrict__ tb = (const __half2*)table_ + ((size_t)li << LOG2T);
            t0 = __ldg(tb + i0);  t1 = __ldg(tb + i1);
            t2 = __ldg(tb + i2);  t3 = __ldg(tb + i3);
            t4 = __ldg(tb + i4);  t5 = __ldg(tb + i5);
            t6 = __ldg(tb + i6);  t7 = __ldg(tb + i7);
        }

        const float ox = 1.f - dx, oy = 1.f - dy, oz = 1.f - dz;

        __half2 acc =              __hmul2(__float2half2_rn((ox * oy) * oz), t0);
        acc = __hadd2(acc, __hmul2(__float2half2_rn((dx * oy) * oz), t1));
        acc = __hadd2(acc, __hmul2(__float2half2_rn((ox * dy) * oz), t2));
        acc = __hadd2(acc, __hmul2(__float2half2_rn((dx * dy) * oz), t3));
        acc = __hadd2(acc, __hmul2(__float2half2_rn((ox * oy) * dz), t4));
        acc = __hadd2(acc, __hmul2(__float2half2_rn((dx * oy) * dz), t5));
        acc = __hadd2(acc, __hmul2(__float2half2_rn((ox * dy) * dz), t6));
        acc = __hadd2(acc, __hmul2(__float2half2_rn((dx * dy) * dz), t7));

        __stcs(&g_feat[(size_t)li * NPTS + pt], acc);   // streaming: don't pollute L2
    }
}

// ---------------- MLP over staged features (FFMA2) ----------------
__global__ __launch_bounds__(256) void k_mlp(
    const void* __restrict__ W1_,
    const void* __restrict__ W2_,
    void*       __restrict__ out_,
    int n)
{
    __shared__ __align__(16) float W1f[INDIM * HID];
    __shared__ __align__(16) float W2f[HID * 4];

    const bool f32mode = probe_f32(W2_);

    if (f32mode) {
        const float* W1s = (const float*)W1_;
        const float* W2s = (const float*)W2_;
        for (int i = threadIdx.x; i < INDIM * HID; i += 256) W1f[i] = W1s[i];
        for (int i = threadIdx.x; i < HID * 4;   i += 256) W2f[i] = W2s[i];
    } else {
        const __half* W1s = (const __half*)W1_;
        const __half* W2s = (const __half*)W2_;
        for (int i = threadIdx.x; i < INDIM * HID; i += 256) W1f[i] = __half2float(W1s[i]);
        for (int i = threadIdx.x; i < HID * 4;   i += 256) W2f[i] = __half2float(W2s[i]);
    }
    __syncthreads();

    const int pt = blockIdx.x * 256 + threadIdx.x;
    if (pt >= n) return;

    __half2 featp[NLVL];
    #pragma unroll
    for (int l = 0; l < NLVL; ++l)
        featp[l] = __ldcs(&g_feat[(size_t)l * NPTS + pt]);

    // R8 ordering preserved exactly; packed pairs keep per-accumulator
    // sequences identical (each lane of f32x2 is an independent accumulator).
    float oh[2][4];
    #pragma unroll
    for (int h = 0; h < 2; ++h) {
        const int hbase = h * 32;
        uint64_t o01 = pk2(0.f, 0.f), o23 = pk2(0.f, 0.f);

        #pragma unroll 1
        for (int cb = 0; cb < 32; cb += 8) {
            uint64_t hh2[4];
            #pragma unroll
            for (int j2 = 0; j2 < 4; ++j2) hh2[j2] = pk2(0.f, 0.f);

            #pragma unroll
            for (int lp = 0; lp < NLVL; ++lp) {
                const float2 fv = __half22float2(featp[lp]);
                const uint64_t fvx = pk2(fv.x, fv.x);
                const uint64_t fvy = pk2(fv.y, fv.y);
                const uint64_t* __restrict__ w0p =
                    (const uint64_t*)&W1f[(2 * lp)     * HID + hbase + cb];
                const uint64_t* __restrict__ w1p =
                    (const uint64_t*)&W1f[(2 * lp + 1) * HID + hbase + cb];
                #pragma unroll
                for (int j2 = 0; j2 < 4; ++j2) {
                    ffma2(hh2[j2], fvx, w0p[j2]);
                    ffma2(hh2[j2], fvy, w1p[j2]);
                }
            }

            #pragma unroll
            for (int j2 = 0; j2 < 4; ++j2) {
                const float2 hp = upk2(hh2[j2]);
                #pragma unroll
                for (int k = 0; k < 2; ++k) {
                    const int jj = 2 * j2 + k;
                    const float hv = h_rt(fmaxf(k ? hp.y : hp.x, 0.f));
                    const uint64_t hv2 = pk2(hv, hv);
                    const uint64_t* __restrict__ w2p =
                        (const uint64_t*)&W2f[(hbase + cb + jj) * 4];
                    ffma2(o01, hv2, w2p[0]);
                    ffma2(o23, hv2, w2p[1]);
                }
            }
        }
        const float2 a01 = upk2(o01), a23 = upk2(o23);
        oh[h][0] = a01.x; oh[h][1] = a01.y; oh[h][2] = a23.x; oh[h][3] = a23.y;
    }

    const float o0 = oh[0][0] + oh[1][0];
    const float o1 = oh[0][1] + oh[1][1];
    const float o2 = oh[0][2] + oh[1][2];
    const float o3 = oh[0][3] + oh[1][3];

    if (f32mode) {
        float4* o = (float4*)out_;
        o[pt] = make_float4(h_rt(o0), h_rt(o1), h_rt(o2), h_rt(o3));
    } else {
        __half2* o = (__half2*)out_;
        o[2 * pt + 0] = __halves2half2(__float2half_rn(o0), __float2half_rn(o1));
        o[2 * pt + 1] = __halves2half2(__float2half_rn(o2), __float2half_rn(o3));
    }
}

extern "C" void kernel_launch(void* const* d_in, const int* in_sizes, int n_in,
                              void* d_out, int out_size) {
    const float* x     = nullptr;  int x_elems = 0;
    const void*  table = nullptr;
    const void*  W1    = nullptr;
    const void*  W2    = nullptr;

    for (int i = 0; i < n_in; ++i) {
        const long long sz = in_sizes[i];
        if (sz == 671088640LL)      table = d_in[i];
        else if (sz == 1572864LL) { x = (const float*)d_in[i]; x_elems = (int)sz; }
        else if (sz == 2560LL)      W1 = d_in[i];
        else if (sz == 256LL)       W2 = d_in[i];
    }
    for (int i = 0; i < n_in; ++i) {
        const long long sz = in_sizes[i];
        if (!table && sz > 100000000LL) table = d_in[i];
        else if (!x && sz > 100000LL && sz <= 100000000LL) { x = (const float*)d_in[i]; x_elems = (int)sz; }
        else if (!W1 && sz > 1000LL && sz <= 100000LL) W1 = d_in[i];
        else if (!W2 && sz <= 1000LL) W2 = d_in[i];
    }

    int n = x_elems / 3;
    if (n > NPTS) n = NPTS;

    ResParams rp;
    for (int l = 0; l < NLVL; ++l)
        rp.r[l] = (float)floor(16.0 * pow(1.3819, (double)l));

    const int egrid = (n + 255) / 256;

    k_encode<7><<<egrid, 256>>>(x, table, W2, 0, n, rp);   // levels 0-6: L2-phased
    k_encode<1><<<egrid, 256>>>(x, table, W2, 7, n, rp);   // level 7: L2-phased
    k_encode<12><<<egrid, 256>>>(x, table, W2, 8, n, rp);  // levels 8-19: streaming

    k_mlp<<<egrid, 256>>>(W1, W2, d_out, n);
}

// round 10
// speedup vs baseline: 1.4295x; 1.4295x over previous
#include <cuda_runtime.h>
#include <cuda_fp16.h>
#include <math.h>
#include <stdint.h>

// R10: bid-ordered level phasing + fused final MLP.
//  - Levels 0-5: one small kernel (combined footprint tiny, L2/L1 resident).
//  - Levels 6-18: ONE kernel, grid = 13 levels x 2048 blocks. Blocks issue in
//    bid order -> each ~1184-CTA wave covers one level -> per-level L2
//    residency (R8's measured win) WITHOUT 13 launch tails, and the thread
//    body stays small (dynamic level, no 12-level unroll -- the R9 mistake).
//  - Level 19 is gathered INLINE in the MLP kernel (hidden under FMA work).
//  - MLP: FFMA2 with LDS.128 weight loads (halves the LDS instruction count
//    that bound R9's k_mlp at L1=84.5%). Per-accumulator order identical to
//    R8/R9 -> rel_err must remain 6.8627e-4.

#define NLVL   20
#define LOG2T  24
#define TMASK  ((1u << LOG2T) - 1u)
#define PRIME1 2654435761u
#define PRIME2 805459861u
#define INDIM  40
#define HID    64
#define NPTS   524288

struct ResParams { float r[NLVL]; };

__device__ __half2 g_feat[NLVL * NPTS];   // level-major scratch (42 MB)

__device__ __forceinline__ float h_rt(float v) {
    return __half2float(__float2half_rn(v));
}

__device__ __forceinline__ bool probe_f32(const void* W2_) {
    const float* w2p = (const float*)W2_;
    int votes = 0;
    #pragma unroll
    for (int i = 0; i < 8; ++i) {
        const float v = __ldg(w2p + i);
        if (isfinite(v) && fabsf(v) >= 2e-3f && fabsf(v) <= 8.0f) ++votes;
    }
    return votes >= 4;
}

// ---- f32x2 packed helpers (FFMA2) ----
__device__ __forceinline__ uint64_t pk2(float lo, float hi) {
    uint64_t r; asm("mov.b64 %0, {%1,%2};" : "=l"(r) : "f"(lo), "f"(hi)); return r;
}
__device__ __forceinline__ float2 upk2(uint64_t v) {
    float2 f; asm("mov.b64 {%0,%1}, %2;" : "=f"(f.x), "=f"(f.y) : "l"(v)); return f;
}
__device__ __forceinline__ void ffma2(uint64_t& d, uint64_t a, uint64_t b) {
    asm("fma.rn.f32x2 %0, %1, %2, %0;" : "+l"(d) : "l"(a), "l"(b));
}

// ---- one level's gather+interp (bit-identical reference fp16 chain) ----
__device__ __forceinline__ __half2 encode_level(
    float px, float py, float pz, float rf,
    const void* __restrict__ table_, int li, bool f32mode)
{
    const float fx = px * rf, fy = py * rf, fz = pz * rf;
    const float gx = floorf(fx), gy = floorf(fy), gz = floorf(fz);
    const float dx = fx - gx, dy = fy - gy, dz = fz - gz;
    const unsigned bx = (unsigned)gx;
    const unsigned by = (unsigned)gy;
    const unsigned bz = (unsigned)gz;
    const unsigned hy0 = by * PRIME1, hy1 = hy0 + PRIME1;
    const unsigned hz0 = bz * PRIME2, hz1 = hz0 + PRIME2;
    const unsigned bx1 = bx + 1u;

    const unsigned i0 = (bx  ^ hy0 ^ hz0) & TMASK;
    const unsigned i1 = (bx1 ^ hy0 ^ hz0) & TMASK;
    const unsigned i2 = (bx  ^ hy1 ^ hz0) & TMASK;
    const unsigned i3 = (bx1 ^ hy1 ^ hz0) & TMASK;
    const unsigned i4 = (bx  ^ hy0 ^ hz1) & TMASK;
    const unsigned i5 = (bx1 ^ hy0 ^ hz1) & TMASK;
    const unsigned i6 = (bx  ^ hy1 ^ hz1) & TMASK;
    const unsigned i7 = (bx1 ^ hy1 ^ hz1) & TMASK;

    __half2 t0, t1, t2, t3, t4, t5, t6, t7;
    if (f32mode) {
        const float2* __restrict__ tb = (const float2*)table_ + ((size_t)li << LOG2T);
        const float2 f0 = __ldg(tb + i0);
        const float2 f1 = __ldg(tb + i1);
        const float2 f2 = __ldg(tb + i2);
        const float2 f3 = __ldg(tb + i3);
        const float2 f4 = __ldg(tb + i4);
        const float2 f5 = __ldg(tb + i5);
        const float2 f6 = __ldg(tb + i6);
        const float2 f7 = __ldg(tb + i7);
        t0 = __floats2half2_rn(f0.x, f0.y);
        t1 = __floats2half2_rn(f1.x, f1.y);
        t2 = __floats2half2_rn(f2.x, f2.y);
        t3 = __floats2half2_rn(f3.x, f3.y);
        t4 = __floats2half2_rn(f4.x, f4.y);
        t5 = __floats2half2_rn(f5.x, f5.y);
        t6 = __floats2half2_rn(f6.x, f6.y);
        t7 = __floats2half2_rn(f7.x, f7.y);
    } else {
        const __half2* __restrict__ tb = (const __half2*)table_ + ((size_t)li << LOG2T);
        t0 = __ldg(tb + i0);  t1 = __ldg(tb + i1);
        t2 = __ldg(tb + i2);  t3 = __ldg(tb + i3);
        t4 = __ldg(tb + i4);  t5 = __ldg(tb + i5);
        t6 = __ldg(tb + i6);  t7 = __ldg(tb + i7);
    }

    const float ox = 1.f - dx, oy = 1.f - dy, oz = 1.f - dz;

    __half2 acc =              __hmul2(__float2half2_rn((ox * oy) * oz), t0);
    acc = __hadd2(acc, __hmul2(__float2half2_rn((dx * oy) * oz), t1));
    acc = __hadd2(acc, __hmul2(__float2half2_rn((ox * dy) * oz), t2));
    acc = __hadd2(acc, __hmul2(__float2half2_rn((dx * dy) * oz), t3));
    acc = __hadd2(acc, __hmul2(__float2half2_rn((ox * oy) * dz), t4));
    acc = __hadd2(acc, __hmul2(__float2half2_rn((dx * oy) * dz), t5));
    acc = __hadd2(acc, __hmul2(__float2half2_rn((ox * dy) * dz), t6));
    acc = __hadd2(acc, __hmul2(__float2half2_rn((dx * dy) * dz), t7));
    return acc;
}

// ---------------- low levels 0..5: one kernel, per-thread unroll ----------------
__global__ __launch_bounds__(256) void k_enc_low(
    const float* __restrict__ xin,
    const void*  __restrict__ table_,
    const void*  __restrict__ W2_,
    int n, ResParams rp)
{
    const int pt = blockIdx.x * 256 + threadIdx.x;
    if (pt >= n) return;
    const bool f32mode = probe_f32(W2_);

    const float px = __ldg(xin + 3 * pt + 0);
    const float py = __ldg(xin + 3 * pt + 1);
    const float pz = __ldg(xin + 3 * pt + 2);

    #pragma unroll
    for (int li = 0; li < 6; ++li) {
        const __half2 acc = encode_level(px, py, pz, rp.r[li], table_, li, f32mode);
        __stcs(&g_feat[(size_t)li * NPTS + pt], acc);
    }
}

// -------- levels [l0, l0+nlvls): one kernel, one level per block-group --------
// Blocks issue in bid order -> each ~full wave handles one level -> per-level
// L2 residency without per-level launch tails.
__global__ __launch_bounds__(256) void k_enc_phased(
    const float* __restrict__ xin,
    const void*  __restrict__ table_,
    const void*  __restrict__ W2_,
    int l0, int bpl, int n, ResParams rp)
{
    const int li = l0 + blockIdx.x / bpl;
    const int pt = (blockIdx.x % bpl) * 256 + threadIdx.x;
    if (pt >= n) return;
    const bool f32mode = probe_f32(W2_);

    const float px = __ldg(xin + 3 * pt + 0);
    const float py = __ldg(xin + 3 * pt + 1);
    const float pz = __ldg(xin + 3 * pt + 2);

    const __half2 acc = encode_level(px, py, pz, rp.r[li], table_, li, f32mode);
    __stcs(&g_feat[(size_t)li * NPTS + pt], acc);
}

// -------- final: level 19 gather inline + MLP (FFMA2, LDS.128 weights) --------
__global__ __launch_bounds__(256) void k_mlp_final(
    const float* __restrict__ xin,
    const void*  __restrict__ table_,
    const void*  __restrict__ W1_,
    const void*  __restrict__ W2_,
    void*        __restrict__ out_,
    int n, ResParams rp)
{
    __shared__ __align__(16) float W1f[INDIM * HID];
    __shared__ __align__(16) float W2f[HID * 4];

    const bool f32mode = probe_f32(W2_);

    if (f32mode) {
        const float* W1s = (const float*)W1_;
        const float* W2s = (const float*)W2_;
        for (int i = threadIdx.x; i < INDIM * HID; i += 256) W1f[i] = W1s[i];
        for (int i = threadIdx.x; i < HID * 4;   i += 256) W2f[i] = W2s[i];
    } else {
        const __half* W1s = (const __half*)W1_;
        const __half* W2s = (const __half*)W2_;
        for (int i = threadIdx.x; i < INDIM * HID; i += 256) W1f[i] = __half2float(W1s[i]);
        for (int i = threadIdx.x; i < HID * 4;   i += 256) W2f[i] = __half2float(W2s[i]);
    }
    __syncthreads();

    const int pt = blockIdx.x * 256 + threadIdx.x;
    if (pt >= n) return;

    const float px = __ldg(xin + 3 * pt + 0);
    const float py = __ldg(xin + 3 * pt + 1);
    const float pz = __ldg(xin + 3 * pt + 2);

    __half2 featp[NLVL];
    // level 19 inline (its gather latency hides under the FMA work below)
    featp[19] = encode_level(px, py, pz, rp.r[19], table_, 19, f32mode);
    #pragma unroll
    for (int l = 0; l < 19; ++l)
        featp[l] = __ldcs(&g_feat[(size_t)l * NPTS + pt]);

    // MLP, per-accumulator order identical to R8/R9 (rel_err 6.8627e-4).
    float oh[2][4];
    #pragma unroll
    for (int h = 0; h < 2; ++h) {
        const int hbase = h * 32;
        uint64_t o01 = pk2(0.f, 0.f), o23 = pk2(0.f, 0.f);

        #pragma unroll 1
        for (int cb = 0; cb < 32; cb += 8) {
            uint64_t hh2[4];
            #pragma unroll
            for (int j2 = 0; j2 < 4; ++j2) hh2[j2] = pk2(0.f, 0.f);

            #pragma unroll
            for (int lp = 0; lp < NLVL; ++lp) {
                const float2 fv = __half22float2(featp[lp]);
                const uint64_t fvx = pk2(fv.x, fv.x);
                const uint64_t fvy = pk2(fv.y, fv.y);
                const ulonglong2* __restrict__ w0p =
                    (const ulonglong2*)&W1f[(2 * lp)     * HID + hbase + cb];
                const ulonglong2* __restrict__ w1p =
                    (const ulonglong2*)&W1f[(2 * lp + 1) * HID + hbase + cb];
                const ulonglong2 a0 = w0p[0], a1 = w0p[1];   // LDS.128 x2
                const ulonglong2 b0 = w1p[0], b1 = w1p[1];   // LDS.128 x2
                ffma2(hh2[0], fvx, a0.x);  ffma2(hh2[0], fvy, b0.x);
                ffma2(hh2[1], fvx, a0.y);  ffma2(hh2[1], fvy, b0.y);
                ffma2(hh2[2], fvx, a1.x);  ffma2(hh2[2], fvy, b1.x);
                ffma2(hh2[3], fvx, a1.y);  ffma2(hh2[3], fvy, b1.y);
            }

            #pragma unroll
            for (int j2 = 0; j2 < 4; ++j2) {
                const float2 hp = upk2(hh2[j2]);
                #pragma unroll
                for (int k = 0; k < 2; ++k) {
                    const int jj = 2 * j2 + k;
                    const float hv = h_rt(fmaxf(k ? hp.y : hp.x, 0.f));
                    const uint64_t hv2 = pk2(hv, hv);
                    const ulonglong2 w2 =
                        *(const ulonglong2*)&W2f[(hbase + cb + jj) * 4];  // LDS.128
                    ffma2(o01, hv2, w2.x);
                    ffma2(o23, hv2, w2.y);
                }
            }
        }
        const float2 a01 = upk2(o01), a23 = upk2(o23);
        oh[h][0] = a01.x; oh[h][1] = a01.y; oh[h][2] = a23.x; oh[h][3] = a23.y;
    }

    const float o0 = oh[0][0] + oh[1][0];
    const float o1 = oh[0][1] + oh[1][1];
    const float o2 = oh[0][2] + oh[1][2];
    const float o3 = oh[0][3] + oh[1][3];

    if (f32mode) {
        float4* o = (float4*)out_;
        o[pt] = make_float4(h_rt(o0), h_rt(o1), h_rt(o2), h_rt(o3));
    } else {
        __half2* o = (__half2*)out_;
        o[2 * pt + 0] = __halves2half2(__float2half_rn(o0), __float2half_rn(o1));
        o[2 * pt + 1] = __halves2half2(__float2half_rn(o2), __float2half_rn(o3));
    }
}

extern "C" void kernel_launch(void* const* d_in, const int* in_sizes, int n_in,
                              void* d_out, int out_size) {
    const float* x     = nullptr;  int x_elems = 0;
    const void*  table = nullptr;
    const void*  W1    = nullptr;
    const void*  W2    = nullptr;

    for (int i = 0; i < n_in; ++i) {
        const long long sz = in_sizes[i];
        if (sz == 671088640LL)      table = d_in[i];
        else if (sz == 1572864LL) { x = (const float*)d_in[i]; x_elems = (int)sz; }
        else if (sz == 2560LL)      W1 = d_in[i];
        else if (sz == 256LL)       W2 = d_in[i];
    }
    for (int i = 0; i < n_in; ++i) {
        const long long sz = in_sizes[i];
        if (!table && sz > 100000000LL) table = d_in[i];
        else if (!x && sz > 100000LL && sz <= 100000000LL) { x = (const float*)d_in[i]; x_elems = (int)sz; }
        else if (!W1 && sz > 1000LL && sz <= 100000LL) W1 = d_in[i];
        else if (!W2 && sz <= 1000LL) W2 = d_in[i];
    }

    int n = x_elems / 3;
    if (n > NPTS) n = NPTS;

    ResParams rp;
    for (int l = 0; l < NLVL; ++l)
        rp.r[l] = (float)floor(16.0 * pow(1.3819, (double)l));

    const int bpl = (n + 255) / 256;          // blocks per level (2048)

    k_enc_low<<<bpl, 256>>>(x, table, W2, n, rp);                    // levels 0-5
    k_enc_phased<<<13 * bpl, 256>>>(x, table, W2, 6, bpl, n, rp);    // levels 6-18, bid-phased
    k_mlp_final<<<bpl, 256>>>(x, table, W1, W2, d_out, n, rp);       // level 19 + MLP
}

// round 11
// speedup vs baseline: 1.7027x; 1.1911x over previous
#include <cuda_runtime.h>
#include <cuda_fp16.h>
#include <math.h>
#include <stdint.h>

// R11: drop the standalone low-level encode kernel (measured 130us of pure
// L2-latency serialization with nothing to hide under). Levels 0-5 and 19 are
// gathered INLINE in the MLP kernel, where their cache-resident gather latency
// hides under ~1280 FFMA2/thread. Levels 6-18 keep R10's bid-ordered phased
// kernel (measured at the compulsory-DRAM floor, ~22us/level).

#define NLVL   20
#define LOG2T  24
#define TMASK  ((1u << LOG2T) - 1u)
#define PRIME1 2654435761u
#define PRIME2 805459861u
#define INDIM  40
#define HID    64
#define NPTS   524288

struct ResParams { float r[NLVL]; };

__device__ __half2 g_feat[NLVL * NPTS];   // level-major scratch (42 MB)

__device__ __forceinline__ float h_rt(float v) {
    return __half2float(__float2half_rn(v));
}

__device__ __forceinline__ bool probe_f32(const void* W2_) {
    const float* w2p = (const float*)W2_;
    int votes = 0;
    #pragma unroll
    for (int i = 0; i < 8; ++i) {
        const float v = __ldg(w2p + i);
        if (isfinite(v) && fabsf(v) >= 2e-3f && fabsf(v) <= 8.0f) ++votes;
    }
    return votes >= 4;
}

// ---- f32x2 packed helpers (FFMA2) ----
__device__ __forceinline__ uint64_t pk2(float lo, float hi) {
    uint64_t r; asm("mov.b64 %0, {%1,%2};" : "=l"(r) : "f"(lo), "f"(hi)); return r;
}
__device__ __forceinline__ float2 upk2(uint64_t v) {
    float2 f; asm("mov.b64 {%0,%1}, %2;" : "=f"(f.x), "=f"(f.y) : "l"(v)); return f;
}
__device__ __forceinline__ void ffma2(uint64_t& d, uint64_t a, uint64_t b) {
    asm("fma.rn.f32x2 %0, %1, %2, %0;" : "+l"(d) : "l"(a), "l"(b));
}

// ---- one level's gather+interp (bit-identical reference fp16 chain) ----
__device__ __forceinline__ __half2 encode_level(
    float px, float py, float pz, float rf,
    const void* __restrict__ table_, int li, bool f32mode)
{
    const float fx = px * rf, fy = py * rf, fz = pz * rf;
    const float gx = floorf(fx), gy = floorf(fy), gz = floorf(fz);
    const float dx = fx - gx, dy = fy - gy, dz = fz - gz;
    const unsigned bx = (unsigned)gx;
    const unsigned by = (unsigned)gy;
    const unsigned bz = (unsigned)gz;
    const unsigned hy0 = by * PRIME1, hy1 = hy0 + PRIME1;
    const unsigned hz0 = bz * PRIME2, hz1 = hz0 + PRIME2;
    const unsigned bx1 = bx + 1u;

    const unsigned i0 = (bx  ^ hy0 ^ hz0) & TMASK;
    const unsigned i1 = (bx1 ^ hy0 ^ hz0) & TMASK;
    const unsigned i2 = (bx  ^ hy1 ^ hz0) & TMASK;
    const unsigned i3 = (bx1 ^ hy1 ^ hz0) & TMASK;
    const unsigned i4 = (bx  ^ hy0 ^ hz1) & TMASK;
    const unsigned i5 = (bx1 ^ hy0 ^ hz1) & TMASK;
    const unsigned i6 = (bx  ^ hy1 ^ hz1) & TMASK;
    const unsigned i7 = (bx1 ^ hy1 ^ hz1) & TMASK;

    __half2 t0, t1, t2, t3, t4, t5, t6, t7;
    if (f32mode) {
        const float2* __restrict__ tb = (const float2*)table_ + ((size_t)li << LOG2T);
        const float2 f0 = __ldg(tb + i0);
        const float2 f1 = __ldg(tb + i1);
        const float2 f2 = __ldg(tb + i2);
        const float2 f3 = __ldg(tb + i3);
        const float2 f4 = __ldg(tb + i4);
        const float2 f5 = __ldg(tb + i5);
        const float2 f6 = __ldg(tb + i6);
        const float2 f7 = __ldg(tb + i7);
        t0 = __floats2half2_rn(f0.x, f0.y);
        t1 = __floats2half2_rn(f1.x, f1.y);
        t2 = __floats2half2_rn(f2.x, f2.y);
        t3 = __floats2half2_rn(f3.x, f3.y);
        t4 = __floats2half2_rn(f4.x, f4.y);
        t5 = __floats2half2_rn(f5.x, f5.y);
        t6 = __floats2half2_rn(f6.x, f6.y);
        t7 = __floats2half2_rn(f7.x, f7.y);
    } else {
        const __half2* __restrict__ tb = (const __half2*)table_ + ((size_t)li << LOG2T);
        t0 = __ldg(tb + i0);  t1 = __ldg(tb + i1);
        t2 = __ldg(tb + i2);  t3 = __ldg(tb + i3);
        t4 = __ldg(tb + i4);  t5 = __ldg(tb + i5);
        t6 = __ldg(tb + i6);  t7 = __ldg(tb + i7);
    }

    const float ox = 1.f - dx, oy = 1.f - dy, oz = 1.f - dz;

    __half2 acc =              __hmul2(__float2half2_rn((ox * oy) * oz), t0);
    acc = __hadd2(acc, __hmul2(__float2half2_rn((dx * oy) * oz), t1));
    acc = __hadd2(acc, __hmul2(__float2half2_rn((ox * dy) * oz), t2));
    acc = __hadd2(acc, __hmul2(__float2half2_rn((dx * dy) * oz), t3));
    acc = __hadd2(acc, __hmul2(__float2half2_rn((ox * oy) * dz), t4));
    acc = __hadd2(acc, __hmul2(__float2half2_rn((dx * oy) * dz), t5));
    acc = __hadd2(acc, __hmul2(__float2half2_rn((ox * dy) * dz), t6));
    acc = __hadd2(acc, __hmul2(__float2half2_rn((dx * dy) * dz), t7));
    return acc;
}

// -------- levels [l0 ...): one level per block-group, bid-ordered phasing --------
__global__ __launch_bounds__(256) void k_enc_phased(
    const float* __restrict__ xin,
    const void*  __restrict__ table_,
    const void*  __restrict__ W2_,
    int l0, int bpl, int n, ResParams rp)
{
    const int li = l0 + blockIdx.x / bpl;
    const int pt = (blockIdx.x % bpl) * 256 + threadIdx.x;
    if (pt >= n) return;
    const bool f32mode = probe_f32(W2_);

    const float px = __ldg(xin + 3 * pt + 0);
    const float py = __ldg(xin + 3 * pt + 1);
    const float pz = __ldg(xin + 3 * pt + 2);

    const __half2 acc = encode_level(px, py, pz, rp.r[li], table_, li, f32mode);
    __stcs(&g_feat[(size_t)li * NPTS + pt], acc);
}

// -------- final: levels 0-5 & 19 gathered inline + MLP (FFMA2, LDS.128) --------
__global__ __launch_bounds__(256) void k_mlp_final(
    const float* __restrict__ xin,
    const void*  __restrict__ table_,
    const void*  __restrict__ W1_,
    const void*  __restrict__ W2_,
    void*        __restrict__ out_,
    int n, ResParams rp)
{
    __shared__ __align__(16) float W1f[INDIM * HID];
    __shared__ __align__(16) float W2f[HID * 4];

    const bool f32mode = probe_f32(W2_);

    if (f32mode) {
        const float* W1s = (const float*)W1_;
        const float* W2s = (const float*)W2_;
        for (int i = threadIdx.x; i < INDIM * HID; i += 256) W1f[i] = W1s[i];
        for (int i = threadIdx.x; i < HID * 4;   i += 256) W2f[i] = W2s[i];
    } else {
        const __half* W1s = (const __half*)W1_;
        const __half* W2s = (const __half*)W2_;
        for (int i = threadIdx.x; i < INDIM * HID; i += 256) W1f[i] = __half2float(W1s[i]);
        for (int i = threadIdx.x; i < HID * 4;   i += 256) W2f[i] = __half2float(W2s[i]);
    }
    __syncthreads();

    const int pt = blockIdx.x * 256 + threadIdx.x;
    if (pt >= n) return;

    const float px = __ldg(xin + 3 * pt + 0);
    const float py = __ldg(xin + 3 * pt + 1);
    const float pz = __ldg(xin + 3 * pt + 2);

    __half2 featp[NLVL];
    // cache-resident levels 0-5 + streaming level 19: gathered here, latency
    // hidden under the FFMA2 wall below.
    #pragma unroll
    for (int l = 0; l < 6; ++l)
        featp[l] = encode_level(px, py, pz, rp.r[l], table_, l, f32mode);
    featp[19] = encode_level(px, py, pz, rp.r[19], table_, 19, f32mode);
    #pragma unroll
    for (int l = 6; l < 19; ++l)
        featp[l] = __ldcs(&g_feat[(size_t)l * NPTS + pt]);

    // MLP, per-accumulator order identical to R8-R10 (rel_err 6.8627e-4).
    float oh[2][4];
    #pragma unroll
    for (int h = 0; h < 2; ++h) {
        const int hbase = h * 32;
        uint64_t o01 = pk2(0.f, 0.f), o23 = pk2(0.f, 0.f);

        #pragma unroll 1
        for (int cb = 0; cb < 32; cb += 8) {
            uint64_t hh2[4];
            #pragma unroll
            for (int j2 = 0; j2 < 4; ++j2) hh2[j2] = pk2(0.f, 0.f);

            #pragma unroll
            for (int lp = 0; lp < NLVL; ++lp) {
                const float2 fv = __half22float2(featp[lp]);
                const uint64_t fvx = pk2(fv.x, fv.x);
                const uint64_t fvy = pk2(fv.y, fv.y);
                const ulonglong2* __restrict__ w0p =
                    (const ulonglong2*)&W1f[(2 * lp)     * HID + hbase + cb];
                const ulonglong2* __restrict__ w1p =
                    (const ulonglong2*)&W1f[(2 * lp + 1) * HID + hbase + cb];
                const ulonglong2 a0 = w0p[0], a1 = w0p[1];   // LDS.128 x2
                const ulonglong2 b0 = w1p[0], b1 = w1p[1];   // LDS.128 x2
                ffma2(hh2[0], fvx, a0.x);  ffma2(hh2[0], fvy, b0.x);
                ffma2(hh2[1], fvx, a0.y);  ffma2(hh2[1], fvy, b0.y);
                ffma2(hh2[2], fvx, a1.x);  ffma2(hh2[2], fvy, b1.x);
                ffma2(hh2[3], fvx, a1.y);  ffma2(hh2[3], fvy, b1.y);
            }

            #pragma unroll
            for (int j2 = 0; j2 < 4; ++j2) {
                const float2 hp = upk2(hh2[j2]);
                #pragma unroll
                for (int k = 0; k < 2; ++k) {
                    const int jj = 2 * j2 + k;
                    const float hv = h_rt(fmaxf(k ? hp.y : hp.x, 0.f));
                    const uint64_t hv2 = pk2(hv, hv);
                    const ulonglong2 w2 =
                        *(const ulonglong2*)&W2f[(hbase + cb + jj) * 4];  // LDS.128
                    ffma2(o01, hv2, w2.x);
                    ffma2(o23, hv2, w2.y);
                }
            }
        }
        const float2 a01 = upk2(o01), a23 = upk2(o23);
        oh[h][0] = a01.x; oh[h][1] = a01.y; oh[h][2] = a23.x; oh[h][3] = a23.y;
    }

    const float o0 = oh[0][0] + oh[1][0];
    const float o1 = oh[0][1] + oh[1][1];
    const float o2 = oh[0][2] + oh[1][2];
    const float o3 = oh[0][3] + oh[1][3];

    if (f32mode) {
        float4* o = (float4*)out_;
        o[pt] = make_float4(h_rt(o0), h_rt(o1), h_rt(o2), h_rt(o3));
    } else {
        __half2* o = (__half2*)out_;
        o[2 * pt + 0] = __halves2half2(__float2half_rn(o0), __float2half_rn(o1));
        o[2 * pt + 1] = __halves2half2(__float2half_rn(o2), __float2half_rn(o3));
    }
}

extern "C" void kernel_launch(void* const* d_in, const int* in_sizes, int n_in,
                              void* d_out, int out_size) {
    const float* x     = nullptr;  int x_elems = 0;
    const void*  table = nullptr;
    const void*  W1    = nullptr;
    const void*  W2    = nullptr;

    for (int i = 0; i < n_in; ++i) {
        const long long sz = in_sizes[i];
        if (sz == 671088640LL)      table = d_in[i];
        else if (sz == 1572864LL) { x = (const float*)d_in[i]; x_elems = (int)sz; }
        else if (sz == 2560LL)      W1 = d_in[i];
        else if (sz == 256LL)       W2 = d_in[i];
    }
    for (int i = 0; i < n_in; ++i) {
        const long long sz = in_sizes[i];
        if (!table && sz > 100000000LL) table = d_in[i];
        else if (!x && sz > 100000LL && sz <= 100000000LL) { x = (const float*)d_in[i]; x_elems = (int)sz; }
        else if (!W1 && sz > 1000LL && sz <= 100000LL) W1 = d_in[i];
        else if (!W2 && sz <= 1000LL) W2 = d_in[i];
    }

    int n = x_elems / 3;
    if (n > NPTS) n = NPTS;

    ResParams rp;
    for (int l = 0; l < NLVL; ++l)
        rp.r[l] = (float)floor(16.0 * pow(1.3819, (double)l));

    const int bpl = (n + 255) / 256;          // blocks per level (2048)

    k_enc_phased<<<13 * bpl, 256>>>(x, table, W2, 6, bpl, n, rp);    // levels 6-18, bid-phased
    k_mlp_final<<<bpl, 256>>>(x, table, W1, W2, d_out, n, rp);       // levels 0-5 + 19 + MLP
}